// round 2
// baseline (speedup 1.0000x reference)
#include <cuda_runtime.h>
#include <math.h>

#define H 4096
#define S 4096
#define NROWS (3 * H)   // 12288 rows per weight matrix

// Scratch (allocation-free rule: __device__ globals)
__device__ float g_y_ih[NROWS];
__device__ float g_y_hh[NROWS];
__device__ float g_P[S];

// ---------------------------------------------------------------------------
// Kernel 1: fused dual GEMV. Virtual 24576-row matrix:
//   rows [0, 12288)      -> w_ih row r   dotted with x
//   rows [12288, 24576)  -> w_hh row r'  dotted with hidden
// One warp per row, 8 rows per 256-thread block. Vector staged in smem.
// ---------------------------------------------------------------------------
__global__ void __launch_bounds__(256) gemv_kernel(
    const float* __restrict__ x, const float* __restrict__ hidden,
    const float* __restrict__ w_ih, const float* __restrict__ w_hh,
    const float* __restrict__ b_ih, const float* __restrict__ b_hh)
{
    __shared__ float4 vs[H / 4];   // 16 KB

    const int rowBase = blockIdx.x * 8;
    const bool isIH = rowBase < NROWS;   // blocks never straddle: 12288 % 8 == 0

    const float* vec = isIH ? x : hidden;
    for (int i = threadIdx.x; i < H / 4; i += blockDim.x)
        vs[i] = reinterpret_cast<const float4*>(vec)[i];
    __syncthreads();

    const int warp = threadIdx.x >> 5;
    const int lane = threadIdx.x & 31;
    const int r    = rowBase + warp;
    const int lr   = isIH ? r : (r - NROWS);

    const float* W    = isIH ? w_ih : w_hh;
    const float* bias = isIH ? b_ih : b_hh;
    float*       yout = isIH ? g_y_ih : g_y_hh;

    const float4* wrow = reinterpret_cast<const float4*>(W + (size_t)lr * H);

    float acc = 0.0f;
#pragma unroll 8
    for (int i = lane; i < H / 4; i += 32) {
        float4 w4 = wrow[i];
        float4 v4 = vs[i];
        acc = fmaf(w4.x, v4.x, acc);
        acc = fmaf(w4.y, v4.y, acc);
        acc = fmaf(w4.z, v4.z, acc);
        acc = fmaf(w4.w, v4.w, acc);
    }
#pragma unroll
    for (int off = 16; off > 0; off >>= 1)
        acc += __shfl_down_sync(0xffffffffu, acc, off);

    if (lane == 0)
        yout[lr] = acc + bias[lr];
}

// ---------------------------------------------------------------------------
// Kernel 2: GRU elementwise -> a[j] = relu(gru_out[j]), then inclusive
// prefix sum P[t] = sum_{k<=t} a[k]. Single block, 1024 threads x 4 elems.
// ---------------------------------------------------------------------------
__global__ void __launch_bounds__(1024) act_scan_kernel(const float* __restrict__ hidden)
{
    __shared__ float warp_sums[32];

    const int tid  = threadIdx.x;
    const int lane = tid & 31;
    const int wid  = tid >> 5;

    float vals[4];
    float local = 0.0f;
#pragma unroll
    for (int k = 0; k < 4; k++) {
        const int j = tid * 4 + k;
        const float i_r = g_y_ih[j];
        const float i_z = g_y_ih[j + H];
        const float i_n = g_y_ih[j + 2 * H];
        const float h_r = g_y_hh[j];
        const float h_z = g_y_hh[j + H];
        const float h_n = g_y_hh[j + 2 * H];

        const float rg = 1.0f / (1.0f + expf(-(i_r + h_r)));
        const float zg = 1.0f / (1.0f + expf(-(i_z + h_z)));
        const float ng = tanhf(i_n + rg * h_n);
        const float b  = (1.0f - zg) * hidden[j] + zg * ng;
        const float a  = fmaxf(b, 0.0f);

        local  += a;
        vals[k] = local;                 // inclusive within thread
    }

    // warp-level inclusive scan of per-thread totals
    float t = local;
#pragma unroll
    for (int off = 1; off < 32; off <<= 1) {
        float n = __shfl_up_sync(0xffffffffu, t, off);
        if (lane >= off) t += n;
    }
    if (lane == 31) warp_sums[wid] = t;
    __syncthreads();

    if (tid < 32) {
        float w = warp_sums[tid];
#pragma unroll
        for (int off = 1; off < 32; off <<= 1) {
            float n = __shfl_up_sync(0xffffffffu, w, off);
            if (tid >= off) w += n;
        }
        warp_sums[tid] = w;
    }
    __syncthreads();

    float base = t - local;              // exclusive within warp
    if (wid > 0) base += warp_sums[wid - 1];

#pragma unroll
    for (int k = 0; k < 4; k++)
        g_P[tid * 4 + k] = base + vals[k];
}

// ---------------------------------------------------------------------------
// Kernel 3: outputs[t][j] = P[t] + hidden[(j - t - 1) mod H].
// hidden is duplicated into 2H smem so the mod becomes a plain offset.
// One block per t-row; coalesced float4 stores. Row t==S-1 also writes
// new_hidden at the tail of d_out when present.
// ---------------------------------------------------------------------------
__global__ void __launch_bounds__(256) write_kernel(
    const float* __restrict__ hidden, float* __restrict__ out, int write_tail)
{
    __shared__ float hs[2 * H];          // 32 KB

    const int t = blockIdx.x;
    for (int i = threadIdx.x; i < 2 * H; i += blockDim.x)
        hs[i] = hidden[i & (H - 1)];
    __syncthreads();

    const float p   = g_P[t];
    const int   off = H - 1 - t >= 0 ? (H - 1 - t) : (2 * H - 1 - t); // (H-1-t) mod H, t<H so first branch except t==... t<=H-1 always
    float* __restrict__ orow = out + (size_t)t * H;

    for (int j4 = threadIdx.x; j4 < H / 4; j4 += blockDim.x) {
        const int j = j4 * 4;
        float4 v;
        v.x = p + hs[j + 0 + off];
        v.y = p + hs[j + 1 + off];
        v.z = p + hs[j + 2 + off];
        v.w = p + hs[j + 3 + off];
        reinterpret_cast<float4*>(orow)[j4] = v;

        if (write_tail && t == S - 1)
            reinterpret_cast<float4*>(out + (size_t)S * H)[j4] = v;
    }
}

extern "C" void kernel_launch(void* const* d_in, const int* in_sizes, int n_in,
                              void* d_out, int out_size)
{
    const float* x      = (const float*)d_in[0];
    const float* hidden = (const float*)d_in[1];
    const float* w_ih   = (const float*)d_in[2];
    const float* w_hh   = (const float*)d_in[3];
    const float* b_ih   = (const float*)d_in[4];
    const float* b_hh   = (const float*)d_in[5];
    float* out = (float*)d_out;

    const int write_tail = ((long long)out_size - (long long)S * H) >= H ? 1 : 0;

    gemv_kernel<<<(2 * NROWS) / 8, 256>>>(x, hidden, w_ih, w_hh, b_ih, b_hh);
    act_scan_kernel<<<1, 1024>>>(hidden);
    write_kernel<<<S, 256>>>(hidden, out, write_tail);
}

// round 3
// speedup vs baseline: 1.1460x; 1.1460x over previous
#include <cuda_runtime.h>
#include <math.h>

#define H 4096
#define S 4096
#define NROWS (3 * H)   // 12288 rows per weight matrix

// Scratch (allocation-free rule: __device__ globals)
__device__ float g_y_ih[NROWS];
__device__ float g_y_hh[NROWS];
__device__ float g_P[S];

// ---------------------------------------------------------------------------
// Kernel 1: fused dual GEMV. Virtual 24576-row matrix:
//   rows [0, 12288)      -> w_ih row r dotted with x
//   rows [12288, 24576)  -> w_hh row r dotted with hidden
// One warp per row, 16 rows per 512-thread block. Vector staged in smem.
// ---------------------------------------------------------------------------
__global__ void __launch_bounds__(512) gemv_kernel(
    const float* __restrict__ x, const float* __restrict__ hidden,
    const float* __restrict__ w_ih, const float* __restrict__ w_hh,
    const float* __restrict__ b_ih, const float* __restrict__ b_hh)
{
    __shared__ float4 vs[H / 4];   // 16 KB

    const int rowBase = blockIdx.x * 16;
    const bool isIH = rowBase < NROWS;   // blocks never straddle: 12288 % 16 == 0

    const float* vec = isIH ? x : hidden;
    for (int i = threadIdx.x; i < H / 4; i += blockDim.x)
        vs[i] = reinterpret_cast<const float4*>(vec)[i];
    __syncthreads();

    const int warp = threadIdx.x >> 5;
    const int lane = threadIdx.x & 31;
    const int r    = rowBase + warp;
    const int lr   = isIH ? r : (r - NROWS);

    const float* W    = isIH ? w_ih : w_hh;
    const float* bias = isIH ? b_ih : b_hh;
    float*       yout = isIH ? g_y_ih : g_y_hh;

    const float4* wrow = reinterpret_cast<const float4*>(W + (size_t)lr * H);

    float acc = 0.0f;
#pragma unroll 8
    for (int i = lane; i < H / 4; i += 32) {
        float4 w4 = wrow[i];
        float4 v4 = vs[i];
        acc = fmaf(w4.x, v4.x, acc);
        acc = fmaf(w4.y, v4.y, acc);
        acc = fmaf(w4.z, v4.z, acc);
        acc = fmaf(w4.w, v4.w, acc);
    }
#pragma unroll
    for (int off = 16; off > 0; off >>= 1)
        acc += __shfl_down_sync(0xffffffffu, acc, off);

    if (lane == 0)
        yout[lr] = acc + bias[lr];
}

// ---------------------------------------------------------------------------
// Kernel 2: GRU elementwise -> a[j] = relu(gru_out[j]), then inclusive
// prefix sum P[t] = sum_{k<=t} a[k]. Single block, 1024 threads x 4 elems.
// float4 loads, fast-math intrinsics (rel-err budget is 1e-3).
// ---------------------------------------------------------------------------
__global__ void __launch_bounds__(1024) act_scan_kernel(const float* __restrict__ hidden)
{
    __shared__ float warp_sums[32];

    const int tid  = threadIdx.x;
    const int lane = tid & 31;
    const int wid  = tid >> 5;

    // vectorized loads: j = tid*4 .. tid*4+3 contiguous
    const float4 ir4 = reinterpret_cast<const float4*>(g_y_ih)[tid];
    const float4 iz4 = reinterpret_cast<const float4*>(g_y_ih + H)[tid];
    const float4 in4 = reinterpret_cast<const float4*>(g_y_ih + 2 * H)[tid];
    const float4 hr4 = reinterpret_cast<const float4*>(g_y_hh)[tid];
    const float4 hz4 = reinterpret_cast<const float4*>(g_y_hh + H)[tid];
    const float4 hn4 = reinterpret_cast<const float4*>(g_y_hh + 2 * H)[tid];
    const float4 hh4 = reinterpret_cast<const float4*>(hidden)[tid];

    float irs[4] = {ir4.x, ir4.y, ir4.z, ir4.w};
    float izs[4] = {iz4.x, iz4.y, iz4.z, iz4.w};
    float ins[4] = {in4.x, in4.y, in4.z, in4.w};
    float hrs[4] = {hr4.x, hr4.y, hr4.z, hr4.w};
    float hzs[4] = {hz4.x, hz4.y, hz4.z, hz4.w};
    float hns[4] = {hn4.x, hn4.y, hn4.z, hn4.w};
    float hhs[4] = {hh4.x, hh4.y, hh4.z, hh4.w};

    float vals[4];
    float local = 0.0f;
#pragma unroll
    for (int k = 0; k < 4; k++) {
        const float rg = 1.0f / (1.0f + __expf(-(irs[k] + hrs[k])));
        const float zg = 1.0f / (1.0f + __expf(-(izs[k] + hzs[k])));
        const float ng = tanhf(ins[k] + rg * hns[k]);
        const float b  = (1.0f - zg) * hhs[k] + zg * ng;
        const float a  = fmaxf(b, 0.0f);

        local  += a;
        vals[k] = local;                 // inclusive within thread
    }

    // warp-level inclusive scan of per-thread totals
    float t = local;
#pragma unroll
    for (int off = 1; off < 32; off <<= 1) {
        float n = __shfl_up_sync(0xffffffffu, t, off);
        if (lane >= off) t += n;
    }
    if (lane == 31) warp_sums[wid] = t;
    __syncthreads();

    if (tid < 32) {
        float w = warp_sums[tid];
#pragma unroll
        for (int off = 1; off < 32; off <<= 1) {
            float n = __shfl_up_sync(0xffffffffu, w, off);
            if (tid >= off) w += n;
        }
        warp_sums[tid] = w;
    }
    __syncthreads();

    float base = t - local;              // exclusive within warp
    if (wid > 0) base += warp_sums[wid - 1];

    float4 o;
    o.x = base + vals[0];
    o.y = base + vals[1];
    o.z = base + vals[2];
    o.w = base + vals[3];
    reinterpret_cast<float4*>(g_P)[tid] = o;
}

// ---------------------------------------------------------------------------
// Kernel 3: outputs[t][j] = P[t] + hidden[(j - t - 1) mod H].
// No smem, no syncthreads: hidden is 16 KB and stays L1/L2-resident.
// 128-thread blocks, one block per t-row, pure float4 streaming stores.
// Row t==S-1 also writes new_hidden at the tail of d_out when present.
// ---------------------------------------------------------------------------
__global__ void __launch_bounds__(128) write_kernel(
    const float* __restrict__ hidden, float* __restrict__ out, int write_tail)
{
    const int t   = blockIdx.x;
    const int off = H - 1 - t >= 0 ? (H - 1 - t) : (H - 1 - t + H); // t in [0,S)
    const float p = g_P[t];
    float* __restrict__ orow = out + (size_t)t * H;

#pragma unroll 4
    for (int j4 = threadIdx.x; j4 < H / 4; j4 += 128) {
        const int j = j4 * 4;
        float4 v;
        v.x = p + __ldg(&hidden[(j + 0 + off) & (H - 1)]);
        v.y = p + __ldg(&hidden[(j + 1 + off) & (H - 1)]);
        v.z = p + __ldg(&hidden[(j + 2 + off) & (H - 1)]);
        v.w = p + __ldg(&hidden[(j + 3 + off) & (H - 1)]);
        reinterpret_cast<float4*>(orow)[j4] = v;

        if (write_tail && t == S - 1)
            reinterpret_cast<float4*>(out + (size_t)S * H)[j4] = v;
    }
}

extern "C" void kernel_launch(void* const* d_in, const int* in_sizes, int n_in,
                              void* d_out, int out_size)
{
    const float* x      = (const float*)d_in[0];
    const float* hidden = (const float*)d_in[1];
    const float* w_ih   = (const float*)d_in[2];
    const float* w_hh   = (const float*)d_in[3];
    const float* b_ih   = (const float*)d_in[4];
    const float* b_hh   = (const float*)d_in[5];
    float* out = (float*)d_out;

    const int write_tail = ((long long)out_size - (long long)S * H) >= H ? 1 : 0;

    gemv_kernel<<<(2 * NROWS) / 16, 512>>>(x, hidden, w_ih, w_hh, b_ih, b_hh);
    act_scan_kernel<<<1, 1024>>>(hidden);
    write_kernel<<<S, 128>>>(hidden, out, write_tail);
}

// round 4
// speedup vs baseline: 1.3248x; 1.1561x over previous
#include <cuda_runtime.h>
#include <math.h>

#define H 4096
#define S 4096
#define NROWS (3 * H)   // 12288 rows per weight matrix
#define NCHUNK 32       // act/scan chunks (H / 128)

// Scratch (allocation-free rule: __device__ globals)
__device__ float g_y_ih[NROWS];
__device__ float g_y_hh[NROWS];
__device__ float g_P[S];        // chunk-local inclusive prefix of a[]
__device__ float g_bsum[NCHUNK];
__device__ float g_boff[NCHUNK]; // exclusive prefix of chunk sums

// ---------------------------------------------------------------------------
// Kernel 1: fused dual GEMV. Virtual 24576-row matrix:
//   rows [0, 12288)      -> w_ih row r dotted with x
//   rows [12288, 24576)  -> w_hh row r dotted with hidden
// One warp per row, 16 rows per 512-thread block. Vector staged in smem.
// Weights are read-once: __ldcs (evict-first) keeps them out of L2's way.
// ---------------------------------------------------------------------------
__global__ void __launch_bounds__(512) gemv_kernel(
    const float* __restrict__ x, const float* __restrict__ hidden,
    const float* __restrict__ w_ih, const float* __restrict__ w_hh,
    const float* __restrict__ b_ih, const float* __restrict__ b_hh)
{
    __shared__ float4 vs[H / 4];   // 16 KB

    const int rowBase = blockIdx.x * 16;
    const bool isIH = rowBase < NROWS;   // blocks never straddle: 12288 % 16 == 0

    const float* vec = isIH ? x : hidden;
    for (int i = threadIdx.x; i < H / 4; i += blockDim.x)
        vs[i] = reinterpret_cast<const float4*>(vec)[i];
    __syncthreads();

    const int warp = threadIdx.x >> 5;
    const int lane = threadIdx.x & 31;
    const int r    = rowBase + warp;
    const int lr   = isIH ? r : (r - NROWS);

    const float* W    = isIH ? w_ih : w_hh;
    const float* bias = isIH ? b_ih : b_hh;
    float*       yout = isIH ? g_y_ih : g_y_hh;

    const float4* wrow = reinterpret_cast<const float4*>(W + (size_t)lr * H);

    float acc = 0.0f;
#pragma unroll 8
    for (int i = lane; i < H / 4; i += 32) {
        float4 w4 = __ldcs(&wrow[i]);
        float4 v4 = vs[i];
        acc = fmaf(w4.x, v4.x, acc);
        acc = fmaf(w4.y, v4.y, acc);
        acc = fmaf(w4.z, v4.z, acc);
        acc = fmaf(w4.w, v4.w, acc);
    }
#pragma unroll
    for (int off = 16; off > 0; off >>= 1)
        acc += __shfl_down_sync(0xffffffffu, acc, off);

    if (lane == 0)
        yout[lr] = acc + bias[lr];
}

// ---------------------------------------------------------------------------
// Kernel 2a: GRU elementwise + chunk-local inclusive scan.
// 32 blocks x 128 threads, one element per thread. g_P gets the
// within-chunk inclusive prefix; g_bsum gets each chunk's total.
// ---------------------------------------------------------------------------
__global__ void __launch_bounds__(128) act_kernel(const float* __restrict__ hidden)
{
    __shared__ float warp_sums[4];

    const int tid  = threadIdx.x;
    const int lane = tid & 31;
    const int wid  = tid >> 5;
    const int j    = blockIdx.x * 128 + tid;

    const float i_r = g_y_ih[j];
    const float i_z = g_y_ih[j + H];
    const float i_n = g_y_ih[j + 2 * H];
    const float h_r = g_y_hh[j];
    const float h_z = g_y_hh[j + H];
    const float h_n = g_y_hh[j + 2 * H];

    const float rg = 1.0f / (1.0f + __expf(-(i_r + h_r)));
    const float zg = 1.0f / (1.0f + __expf(-(i_z + h_z)));
    const float ng = tanhf(i_n + rg * h_n);
    const float b  = (1.0f - zg) * hidden[j] + zg * ng;
    float a = fmaxf(b, 0.0f);

    // warp inclusive scan
    float t = a;
#pragma unroll
    for (int off = 1; off < 32; off <<= 1) {
        float n = __shfl_up_sync(0xffffffffu, t, off);
        if (lane >= off) t += n;
    }
    if (lane == 31) warp_sums[wid] = t;
    __syncthreads();

    float base = 0.0f;
#pragma unroll
    for (int w = 0; w < 4; w++)
        if (w < wid) base += warp_sums[w];

    g_P[j] = base + t;
    if (tid == 127)
        g_bsum[blockIdx.x] = base + t;
}

// ---------------------------------------------------------------------------
// Kernel 2b: one warp scans 32 chunk sums into exclusive offsets.
// ---------------------------------------------------------------------------
__global__ void scan_sums_kernel()
{
    const int lane = threadIdx.x;
    const float v = g_bsum[lane];
    float t = v;
#pragma unroll
    for (int off = 1; off < 32; off <<= 1) {
        float n = __shfl_up_sync(0xffffffffu, t, off);
        if (lane >= off) t += n;
    }
    g_boff[lane] = t - v;   // exclusive
}

// ---------------------------------------------------------------------------
// Kernel 3: outputs[t][j] = P[t] + hidden[(j - t - 1) mod H].
// No smem, no syncthreads: hidden is 16 KB and stays L1/L2-resident.
// 4 rows per 256-thread block; pure float4 streaming stores.
// Row t==S-1 also writes new_hidden at the tail of d_out when present.
// ---------------------------------------------------------------------------
__global__ void __launch_bounds__(256) write_kernel(
    const float* __restrict__ hidden, float* __restrict__ out, int write_tail)
{
    const int t0 = blockIdx.x * 4;

#pragma unroll
    for (int r = 0; r < 4; r++) {
        const int t   = t0 + r;
        const int off = H - 1 - t;                 // t < H, so >= 0
        const float p = g_P[t] + g_boff[t >> 7];
        float* __restrict__ orow = out + (size_t)t * H;

#pragma unroll
        for (int it = 0; it < (H / 4) / 256; it++) {   // 4 iterations
            const int j4 = it * 256 + threadIdx.x;
            const int j  = j4 * 4;
            float4 v;
            v.x = p + __ldg(&hidden[(j + 0 + off) & (H - 1)]);
            v.y = p + __ldg(&hidden[(j + 1 + off) & (H - 1)]);
            v.z = p + __ldg(&hidden[(j + 2 + off) & (H - 1)]);
            v.w = p + __ldg(&hidden[(j + 3 + off) & (H - 1)]);
            reinterpret_cast<float4*>(orow)[j4] = v;

            if (write_tail && t == S - 1)
                reinterpret_cast<float4*>(out + (size_t)S * H)[j4] = v;
        }
    }
}

extern "C" void kernel_launch(void* const* d_in, const int* in_sizes, int n_in,
                              void* d_out, int out_size)
{
    const float* x      = (const float*)d_in[0];
    const float* hidden = (const float*)d_in[1];
    const float* w_ih   = (const float*)d_in[2];
    const float* w_hh   = (const float*)d_in[3];
    const float* b_ih   = (const float*)d_in[4];
    const float* b_hh   = (const float*)d_in[5];
    float* out = (float*)d_out;

    const int write_tail = ((long long)out_size - (long long)S * H) >= H ? 1 : 0;

    gemv_kernel<<<(2 * NROWS) / 16, 512>>>(x, hidden, w_ih, w_hh, b_ih, b_hh);
    act_kernel<<<NCHUNK, 128>>>(hidden);
    scan_sums_kernel<<<1, 32>>>();
    write_kernel<<<S / 4, 256>>>(hidden, out, write_tail);
}